// round 7
// baseline (speedup 1.0000x reference)
#include <cuda_runtime.h>
#include <cuda_bf16.h>
#include <cstdint>

#define NNODES 50000
#define NEDGES 200000
#define NGRAPH 2048
#define D_IN   64
#define D_H    1000
#define D_ENC  128

typedef __nv_bfloat16 bf16;

// ---------------- scratch (static device allocations; no cudaMalloc) --------
__device__ float g_aggx [NNODES * D_IN];
__device__ float g_aggy [NNODES * D_ENC];
__device__ float g_h2f  [NNODES * D_ENC];
__device__ float g_aggh2[NNODES * D_ENC];
__device__ float g_z2   [NNODES * 256];   // cols 0..127 rel, 128..255 root
__device__ float g_z4   [NNODES * 128];   // cols 0..63  rel, 64..127  root
__device__ float g_sums [NGRAPH * D_ENC];
__device__ float g_counts[NGRAPH];
__device__ int   g_ei32[2 * NEDGES];
__device__ int   g_batch32[NNODES];
__device__ int   g_is64;

__device__ __align__(16) bf16 g_x_h   [NNODES * D_IN],  g_x_l   [NNODES * D_IN];
__device__ __align__(16) bf16 g_aggx_h[NNODES * D_IN],  g_aggx_l[NNODES * D_IN];
__device__ __align__(16) bf16 g_h1_h  [(size_t)NNODES * D_H], g_h1_l[(size_t)NNODES * D_H];
__device__ __align__(16) bf16 g_h2_h  [NNODES * D_ENC], g_h2_l [NNODES * D_ENC];
__device__ __align__(16) bf16 g_ah2_h [NNODES * D_ENC], g_ah2_l[NNODES * D_ENC];
__device__ __align__(16) bf16 g_w1r_h[D_H * D_IN],  g_w1r_l[D_H * D_IN];
__device__ __align__(16) bf16 g_w1o_h[D_H * D_IN],  g_w1o_l[D_H * D_IN];
__device__ __align__(16) bf16 g_w2_h [256 * D_H],   g_w2_l [256 * D_H];
__device__ __align__(16) bf16 g_w3r_h[D_H * D_ENC], g_w3r_l[D_H * D_ENC];
__device__ __align__(16) bf16 g_w3o_h[D_H * D_ENC], g_w3o_l[D_H * D_ENC];
__device__ __align__(16) bf16 g_w4_h [128 * D_H],   g_w4_l [128 * D_H];

// ---------------- helpers ----------------------------------------------------
__device__ __forceinline__ void split_bf(float v, uint16_t& h, uint16_t& l) {
    bf16 hb = __float2bfloat16(v);
    bf16 lb = __float2bfloat16(v - __bfloat162float(hb));
    h = __bfloat16_as_ushort(hb);
    l = __bfloat16_as_ushort(lb);
}
__device__ __forceinline__ void mma16816(float* d, const uint32_t* a, uint32_t b0, uint32_t b1) {
    asm volatile(
        "mma.sync.aligned.m16n8k16.row.col.f32.bf16.bf16.f32 "
        "{%0,%1,%2,%3}, {%4,%5,%6,%7}, {%8,%9}, {%0,%1,%2,%3};"
        : "+f"(d[0]), "+f"(d[1]), "+f"(d[2]), "+f"(d[3])
        : "r"(a[0]), "r"(a[1]), "r"(a[2]), "r"(a[3]), "r"(b0), "r"(b1));
}
__device__ __forceinline__ uint32_t cvta_s(const void* p) {
    uint32_t a;
    asm("{ .reg .u64 t; cvta.to.shared.u64 t, %1; cvt.u32.u64 %0, t; }" : "=r"(a) : "l"(p));
    return a;
}
#define LDMX4(r, a) \
    asm volatile("ldmatrix.sync.aligned.m8n8.x4.shared.b16 {%0,%1,%2,%3}, [%4];" \
        : "=r"((r)[0]), "=r"((r)[1]), "=r"((r)[2]), "=r"((r)[3]) : "r"(a))

// ---------------- dtype detection + conversion ------------------------------
__global__ void detect_kernel(const int* __restrict__ ei_raw) {
    int odd_zero = 1;
    #pragma unroll
    for (int i = 0; i < 16; ++i)
        if (ei_raw[2 * i + 1] != 0) odd_zero = 0;
    g_is64 = odd_zero;
}
__global__ void convert_kernel(const int* __restrict__ ei_raw, const int* __restrict__ batch_raw) {
    int i = blockIdx.x * blockDim.x + threadIdx.x;
    int is64 = g_is64;
    if (i < 2 * NEDGES) g_ei32[i] = is64 ? ei_raw[2 * i] : ei_raw[i];
    if (i < NNODES)     g_batch32[i] = is64 ? batch_raw[2 * i] : batch_raw[i];
}

// ---------------- merged utility kernels -------------------------------------
__global__ void zero_all_kernel() {
    float4 z = make_float4(0.f, 0.f, 0.f, 0.f);
    float4* aggy  = reinterpret_cast<float4*>(g_aggy);
    float4* aggh2 = reinterpret_cast<float4*>(g_aggh2);
    float4* aggx  = reinterpret_cast<float4*>(g_aggx);
    float4* sums  = reinterpret_cast<float4*>(g_sums);
    float4* cnts  = reinterpret_cast<float4*>(g_counts);
    for (int i = blockIdx.x * blockDim.x + threadIdx.x; i < NNODES * D_ENC / 4;
         i += gridDim.x * blockDim.x) {
        aggy[i] = z;
        aggh2[i] = z;
        if (i < NNODES * D_IN / 4) aggx[i] = z;
        if (i < NGRAPH * D_ENC / 4) sums[i] = z;
        if (i < NGRAPH / 4) cnts[i] = z;
    }
}
__global__ void split_static_kernel(
    const float* __restrict__ w1r, const float* __restrict__ w1o,
    const float* __restrict__ w2r, const float* __restrict__ w2o,
    const float* __restrict__ w3r, const float* __restrict__ w3o,
    const float* __restrict__ w4r, const float* __restrict__ w4o,
    const float* __restrict__ x) {
    const int N1 = D_H * D_IN;
    const int N2 = 128 * D_H;
    const int N3 = D_H * D_ENC;
    const int N4 = 64 * D_H;
    const int TOT = 2 * N1 + 2 * N2 + 2 * N3 + 2 * N4 + NNODES * D_IN;
    for (int i = blockIdx.x * blockDim.x + threadIdx.x; i < TOT;
         i += gridDim.x * blockDim.x) {
        float v; bf16 *dh, *dl; int j = i;
        if (j < N1)            { v = w1r[j]; dh = g_w1r_h + j; dl = g_w1r_l + j; }
        else if ((j -= N1) < N1) { v = w1o[j]; dh = g_w1o_h + j; dl = g_w1o_l + j; }
        else if ((j -= N1) < N2) { v = w2r[j]; dh = g_w2_h + j; dl = g_w2_l + j; }
        else if ((j -= N2) < N2) { v = w2o[j]; dh = g_w2_h + N2 + j; dl = g_w2_l + N2 + j; }
        else if ((j -= N2) < N3) { v = w3r[j]; dh = g_w3r_h + j; dl = g_w3r_l + j; }
        else if ((j -= N3) < N3) { v = w3o[j]; dh = g_w3o_h + j; dl = g_w3o_l + j; }
        else if ((j -= N3) < N4) { v = w4r[j]; dh = g_w4_h + j; dl = g_w4_l + j; }
        else if ((j -= N4) < N4) { v = w4o[j]; dh = g_w4_h + N4 + j; dl = g_w4_l + N4 + j; }
        else { j -= N4;            v = x[j];   dh = g_x_h + j;  dl = g_x_l + j; }
        uint16_t h, l; split_bf(v, h, l);
        *dh = __ushort_as_bfloat16(h);
        *dl = __ushort_as_bfloat16(l);
    }
}
__global__ void split_kernel(const float* __restrict__ src, bf16* __restrict__ hi,
                             bf16* __restrict__ lo, int n) {
    for (int i = blockIdx.x * blockDim.x + threadIdx.x; i < n; i += gridDim.x * blockDim.x) {
        uint16_t h, l;
        split_bf(src[i], h, l);
        hi[i] = __ushort_as_bfloat16(h);
        lo[i] = __ushort_as_bfloat16(l);
    }
}
template <int F>
__global__ void edge_agg_kernel(const float* __restrict__ feat, int featStride,
                                float* __restrict__ out, int outStride) {
    constexpr int V = F / 4;
    int idx = blockIdx.x * blockDim.x + threadIdx.x;
    int e = idx / V;
    int f = (idx % V) * 4;
    if (e >= NEDGES) return;
    int s = g_ei32[e];
    int d = g_ei32[NEDGES + e];
    float4 v = *reinterpret_cast<const float4*>(&feat[(size_t)s * featStride + f]);
    float* o = &out[(size_t)d * outStride + f];
    atomicAdd(o + 0, v.x); atomicAdd(o + 1, v.y);
    atomicAdd(o + 2, v.z); atomicAdd(o + 3, v.w);
}
__global__ void combine_pool_kernel(const float* __restrict__ b2) {
    int idx = blockIdx.x * blockDim.x + threadIdx.x;
    if (idx >= NNODES * D_ENC) return;
    int i = idx >> 7, f = idx & 127;
    float v = fmaxf(g_aggy[idx] + g_z2[(size_t)i * 256 + 128 + f] + b2[f], 0.f);
    g_h2f[idx] = v;
    uint16_t h, l; split_bf(v, h, l);
    g_h2_h[idx] = __ushort_as_bfloat16(h);
    g_h2_l[idx] = __ushort_as_bfloat16(l);
    int b = g_batch32[i];
    atomicAdd(&g_sums[b * D_ENC + f], v);
    if (f == 0) atomicAdd(&g_counts[b], 1.f);
}
__global__ void encoded_kernel(float* __restrict__ enc) {
    int idx = blockIdx.x * blockDim.x + threadIdx.x;
    if (idx >= NGRAPH * D_ENC) return;
    int g = idx >> 7;
    enc[idx] = g_sums[idx] / fmaxf(g_counts[g], 1.f);
}
__global__ void out_init_kernel(float* __restrict__ out, const float* __restrict__ b4) {
    int idx = blockIdx.x * blockDim.x + threadIdx.x;
    if (idx >= NNODES * D_IN) return;
    int i = idx >> 6, f = idx & 63;
    out[idx] = g_z4[(size_t)i * 128 + 64 + f] + b4[f];
}

// ---------------- fused dual-layer GEMM --------------------------------------
// Per CTA: 64-row node strip. Phase1: H[64,1000] = act(dual-A GEMM), bf16 hi/lo.
// Phase2: Z[64,O2] = H @ WP^T (K=1000), fp32.
// Tile 64x128, 8 warps (2m x 4n, warp 32x32), CHUNK=32, 2-stage cp.async.
#define MT    64
#define SROW  80
#define A_SUB (MT * SROW)            // 5120
#define W_SUB (128 * SROW)           // 10240
#define STAGE (2 * A_SUB + 2 * W_SUB) // 30720
#define FSMEM (2 * STAGE)            // 61440

template <bool DUAL, bool RELU, bool BIAS, bool BF16OUT>
__device__ __forceinline__ void gemm_tile(
    uint32_t smemBase, int tid, int rowBase, int colBase, int M, int K, int O,
    const bf16* __restrict__ A1h, const bf16* __restrict__ A1l,
    const bf16* __restrict__ A2h, const bf16* __restrict__ A2l,
    const bf16* __restrict__ W1h, const bf16* __restrict__ W1l,
    const bf16* __restrict__ W2h, const bf16* __restrict__ W2l,
    const float* __restrict__ bias,
    float* __restrict__ Cf, bf16* __restrict__ Ch, bf16* __restrict__ Cl, int ldC) {

    const int wid = tid >> 5, lane = tid & 31;
    const int g = lane >> 2, t = lane & 3;
    const int warpM = (wid & 1) * 32, warpN = (wid >> 1) * 32;

    const int laneRowA = (lane & 7) + ((lane & 8) ? 8 : 0);
    const int aK = (lane & 16) ? 16 : 0;
    const int laneRowW = (lane & 7) + ((lane & 16) ? 8 : 0);
    const int wK = (lane & 8) ? 16 : 0;
    uint32_t aoff[2], woff[2];
    #pragma unroll
    for (int mi = 0; mi < 2; ++mi)
        aoff[mi] = (uint32_t)((warpM + mi * 16 + laneRowA) * SROW + aK);
    #pragma unroll
    for (int p = 0; p < 2; ++p)
        woff[p] = (uint32_t)((warpN + p * 16 + laneRowW) * SROW + wK);

    float acc[2][4][4];
    #pragma unroll
    for (int a = 0; a < 2; ++a)
        #pragma unroll
        for (int b = 0; b < 4; ++b)
            #pragma unroll
            for (int c = 0; c < 4; ++c) acc[a][b][c] = 0.f;

    const int KC = (K + 31) >> 5;
    const int C = (DUAL ? 2 : 1) * KC;

    // ---- chunk loader ----
    auto loadChunk = [&](int i, int stage) {
        int side = DUAL ? (i / KC) : 0;
        int c = i - side * KC;
        int k0 = c << 5;
        const bf16* Ah = (DUAL && side) ? A2h : A1h;
        const bf16* Al = (DUAL && side) ? A2l : A1l;
        const bf16* Wh = (DUAL && side) ? W2h : W1h;
        const bf16* Wl = (DUAL && side) ? W2l : W1l;
        uint32_t sb = smemBase + stage * STAGE;
        #pragma unroll
        for (int j = 0; j < 6; ++j) {
            int idx = tid + j * 256;
            const bf16* src;
            uint32_t dst;
            int ok, gk;
            if (idx < 512) {
                int tile = idx >> 8, r = (idx >> 2) & 63, sg = idx & 3;
                gk = k0 + sg * 8;
                int gr = rowBase + r;
                ok = (gr < M) && (gk + 8 <= K);
                const bf16* base = tile ? Al : Ah;
                src = ok ? base + (size_t)gr * K + gk : base;
                dst = sb + tile * A_SUB + (uint32_t)(r * SROW + sg * 16);
            } else {
                int rel = idx - 512;
                int tile = rel >> 9, r = (rel >> 2) & 127, sg = rel & 3;
                gk = k0 + sg * 8;
                int gw = colBase + r;
                ok = (gw < O) && (gk + 8 <= K);
                const bf16* base = tile ? Wl : Wh;
                src = ok ? base + (size_t)gw * K + gk : base;
                dst = sb + 2 * A_SUB + tile * W_SUB + (uint32_t)(r * SROW + sg * 16);
            }
            int sz = ok ? 16 : 0;
            asm volatile("cp.async.cg.shared.global [%0], [%1], 16, %2;"
                         :: "r"(dst), "l"(src), "r"(sz) : "memory");
        }
        asm volatile("cp.async.commit_group;" ::: "memory");
    };

    auto computeChunk = [&](int stage) {
        uint32_t sb = smemBase + stage * STAGE;
        uint32_t bAh = sb, bAl = sb + A_SUB;
        uint32_t bWh = sb + 2 * A_SUB, bWl = sb + 2 * A_SUB + W_SUB;
        #pragma unroll
        for (int ks = 0; ks < 2; ++ks) {
            uint32_t koff = ks * 32;
            uint32_t ah[2][4], al[2][4];
            #pragma unroll
            for (int mi = 0; mi < 2; ++mi) {
                LDMX4(ah[mi], bAh + aoff[mi] + koff);
                LDMX4(al[mi], bAl + aoff[mi] + koff);
            }
            #pragma unroll
            for (int p = 0; p < 2; ++p) {
                uint32_t w[4];
                LDMX4(w, bWh + woff[p] + koff);
                mma16816(acc[0][2 * p],     ah[0], w[0], w[1]);
                mma16816(acc[1][2 * p],     ah[1], w[0], w[1]);
                mma16816(acc[0][2 * p + 1], ah[0], w[2], w[3]);
                mma16816(acc[1][2 * p + 1], ah[1], w[2], w[3]);
                mma16816(acc[0][2 * p],     al[0], w[0], w[1]);
                mma16816(acc[1][2 * p],     al[1], w[0], w[1]);
                mma16816(acc[0][2 * p + 1], al[0], w[2], w[3]);
                mma16816(acc[1][2 * p + 1], al[1], w[2], w[3]);
                uint32_t wl[4];
                LDMX4(wl, bWl + woff[p] + koff);
                mma16816(acc[0][2 * p],     ah[0], wl[0], wl[1]);
                mma16816(acc[1][2 * p],     ah[1], wl[0], wl[1]);
                mma16816(acc[0][2 * p + 1], ah[0], wl[2], wl[3]);
                mma16816(acc[1][2 * p + 1], ah[1], wl[2], wl[3]);
            }
        }
    };

    loadChunk(0, 0);
    for (int c = 0; c < C; ++c) {
        if (c + 1 < C) {
            loadChunk(c + 1, (c + 1) & 1);
            asm volatile("cp.async.wait_group 1;" ::: "memory");
        } else {
            asm volatile("cp.async.wait_group 0;" ::: "memory");
        }
        __syncthreads();
        computeChunk(c & 1);
        __syncthreads();
    }

    // ---- epilogue ----
    #pragma unroll
    for (int mi = 0; mi < 2; ++mi) {
        #pragma unroll
        for (int half = 0; half < 2; ++half) {
            int row = rowBase + warpM + mi * 16 + g + half * 8;
            if (row >= M) continue;
            #pragma unroll
            for (int ni = 0; ni < 4; ++ni) {
                int col = colBase + warpN + ni * 8 + 2 * t;
                if (col >= O) continue;
                float v0 = acc[mi][ni][half * 2 + 0];
                float v1 = acc[mi][ni][half * 2 + 1];
                if (BIAS) { v0 += bias[col]; if (col + 1 < O) v1 += bias[col + 1]; }
                if (RELU) { v0 = fmaxf(v0, 0.f); v1 = fmaxf(v1, 0.f); }
                bool pair = (col + 1 < O);
                size_t o = (size_t)row * ldC + col;
                if (BF16OUT) {
                    uint16_t h0, l0, h1, l1;
                    split_bf(v0, h0, l0);
                    split_bf(v1, h1, l1);
                    if (pair) {
                        *reinterpret_cast<uint32_t*>(&Ch[o]) = (uint32_t)h0 | ((uint32_t)h1 << 16);
                        *reinterpret_cast<uint32_t*>(&Cl[o]) = (uint32_t)l0 | ((uint32_t)l1 << 16);
                    } else {
                        Ch[o] = __ushort_as_bfloat16(h0);
                        Cl[o] = __ushort_as_bfloat16(l0);
                    }
                } else {
                    if (pair) *reinterpret_cast<float2*>(&Cf[o]) = make_float2(v0, v1);
                    else      Cf[o] = v0;
                }
            }
        }
    }
}

// fused: phase1 H[rows,1000] = act(A1@W1^T + A2@W2^T + b); phase2 Z = H @ WP^T
__global__ void __launch_bounds__(256, 2) fused_kernel(
    const bf16* __restrict__ A1h, const bf16* __restrict__ A1l,
    const bf16* __restrict__ A2h, const bf16* __restrict__ A2l, int K1,
    const bf16* __restrict__ W1h, const bf16* __restrict__ W1l,
    const bf16* __restrict__ W2h, const bf16* __restrict__ W2l,
    const float* __restrict__ bias1,
    bf16* __restrict__ Hh, bf16* __restrict__ Hl,
    const bf16* __restrict__ WPh, const bf16* __restrict__ WPl, int O2,
    float* __restrict__ Z) {

    extern __shared__ char smraw[];
    const uint32_t sb = cvta_s(smraw);
    const int tid = threadIdx.x;
    const int rowBase = blockIdx.x * MT;

    // phase 1: 8 col tiles of O=1000
    for (int cb = 0; cb < 8; ++cb) {
        gemm_tile<true, true, true, true>(
            sb, tid, rowBase, cb * 128, NNODES, K1, D_H,
            A1h, A1l, A2h, A2l, W1h, W1l, W2h, W2l,
            bias1, nullptr, Hh, Hl, D_H);
    }
    __threadfence();
    __syncthreads();
    // phase 2: O2/128 col tiles, K=1000
    const int CT = O2 >> 7;
    for (int ct = 0; ct < CT; ++ct) {
        gemm_tile<false, false, false, false>(
            sb, tid, rowBase, ct * 128, NNODES, D_H, O2,
            Hh, Hl, nullptr, nullptr, WPh, WPl, nullptr, nullptr,
            nullptr, Z, nullptr, nullptr, O2);
    }
}

// ---------------- launch ----------------------------------------------------
extern "C" void kernel_launch(void* const* d_in, const int* in_sizes, int n_in,
                              void* d_out, int out_size) {
    const float* x         = (const float*)d_in[0];
    const int*   ei_raw    = (const int*)d_in[1];
    const int*   batch_raw = (const int*)d_in[2];
    const float* W1_rel = (const float*)d_in[3];
    const float* b1     = (const float*)d_in[4];
    const float* W1_root= (const float*)d_in[5];
    const float* W2_rel = (const float*)d_in[6];
    const float* b2     = (const float*)d_in[7];
    const float* W2_root= (const float*)d_in[8];
    const float* W3_rel = (const float*)d_in[9];
    const float* b3     = (const float*)d_in[10];
    const float* W3_root= (const float*)d_in[11];
    const float* W4_rel = (const float*)d_in[12];
    const float* b4     = (const float*)d_in[13];
    const float* W4_root= (const float*)d_in[14];

    float* out = (float*)d_out;
    float* enc = out + (size_t)NNODES * D_IN;

    float *aggx, *aggy, *h2f, *aggh2, *z2, *z4;
    bf16 *x_h, *x_l, *aggx_h, *aggx_l, *h1_h, *h1_l, *h2_h, *h2_l, *ah2_h, *ah2_l;
    bf16 *w1r_h, *w1r_l, *w1o_h, *w1o_l, *w2_h, *w2_l, *w3r_h, *w3r_l, *w3o_h, *w3o_l, *w4_h, *w4_l;
    cudaGetSymbolAddress((void**)&aggx, g_aggx);   cudaGetSymbolAddress((void**)&aggy, g_aggy);
    cudaGetSymbolAddress((void**)&h2f, g_h2f);     cudaGetSymbolAddress((void**)&aggh2, g_aggh2);
    cudaGetSymbolAddress((void**)&z2, g_z2);       cudaGetSymbolAddress((void**)&z4, g_z4);
    cudaGetSymbolAddress((void**)&x_h, g_x_h);     cudaGetSymbolAddress((void**)&x_l, g_x_l);
    cudaGetSymbolAddress((void**)&aggx_h, g_aggx_h); cudaGetSymbolAddress((void**)&aggx_l, g_aggx_l);
    cudaGetSymbolAddress((void**)&h1_h, g_h1_h);   cudaGetSymbolAddress((void**)&h1_l, g_h1_l);
    cudaGetSymbolAddress((void**)&h2_h, g_h2_h);   cudaGetSymbolAddress((void**)&h2_l, g_h2_l);
    cudaGetSymbolAddress((void**)&ah2_h, g_ah2_h); cudaGetSymbolAddress((void**)&ah2_l, g_ah2_l);
    cudaGetSymbolAddress((void**)&w1r_h, g_w1r_h); cudaGetSymbolAddress((void**)&w1r_l, g_w1r_l);
    cudaGetSymbolAddress((void**)&w1o_h, g_w1o_h); cudaGetSymbolAddress((void**)&w1o_l, g_w1o_l);
    cudaGetSymbolAddress((void**)&w2_h, g_w2_h);   cudaGetSymbolAddress((void**)&w2_l, g_w2_l);
    cudaGetSymbolAddress((void**)&w3r_h, g_w3r_h); cudaGetSymbolAddress((void**)&w3r_l, g_w3r_l);
    cudaGetSymbolAddress((void**)&w3o_h, g_w3o_h); cudaGetSymbolAddress((void**)&w3o_l, g_w3o_l);
    cudaGetSymbolAddress((void**)&w4_h, g_w4_h);   cudaGetSymbolAddress((void**)&w4_l, g_w4_l);

    const int T = 256;
    const int NB = (NNODES + MT - 1) / MT;   // 782

    cudaFuncSetAttribute(fused_kernel, cudaFuncAttributeMaxDynamicSharedMemorySize, FSMEM);

    // ---- setup
    detect_kernel<<<1, 1>>>(ei_raw);
    convert_kernel<<<(2 * NEDGES + T - 1) / T, T>>>(ei_raw, batch_raw);
    zero_all_kernel<<<1024, T>>>();
    split_static_kernel<<<1024, T>>>(W1_rel, W1_root, W2_rel, W2_root,
                                     W3_rel, W3_root, W4_rel, W4_root, x);

    // ---- L1+L2 fused: agg(x); h1 = relu(dual GEMM); z2 = h1 @ w2cat^T
    edge_agg_kernel<64><<<(NEDGES * 16 + T - 1) / T, T>>>(x, D_IN, aggx, D_IN);
    split_kernel<<<1024, T>>>(aggx, aggx_h, aggx_l, NNODES * D_IN);
    fused_kernel<<<NB, T, FSMEM>>>(
        aggx_h, aggx_l, x_h, x_l, D_IN,
        w1r_h, w1r_l, w1o_h, w1o_l, b1,
        h1_h, h1_l,
        w2_h, w2_l, 256, z2);

    // ---- middle: aggregate z2_rel; h2; pool; encoded
    edge_agg_kernel<128><<<(NEDGES * 32 + T - 1) / T, T>>>(z2, 256, aggy, D_ENC);
    combine_pool_kernel<<<(NNODES * D_ENC + T - 1) / T, T>>>(b2);
    encoded_kernel<<<(NGRAPH * D_ENC + T - 1) / T, T>>>(enc);

    // ---- L3+L4 fused: agg(h2); h3 = relu(dual GEMM); z4 = h3 @ w4cat^T
    edge_agg_kernel<128><<<(NEDGES * 32 + T - 1) / T, T>>>(h2f, D_ENC, aggh2, D_ENC);
    split_kernel<<<1024, T>>>(aggh2, ah2_h, ah2_l, NNODES * D_ENC);
    fused_kernel<<<NB, T, FSMEM>>>(
        ah2_h, ah2_l, h2_h, h2_l, D_ENC,
        w3r_h, w3r_l, w3o_h, w3o_l, b3,
        h1_h, h1_l,                      // reuse h1 buffers as h3 staging
        w4_h, w4_l, 128, z4);

    // ---- output
    out_init_kernel<<<(NNODES * D_IN + T - 1) / T, T>>>(out, b4);
    edge_agg_kernel<64><<<(NEDGES * 16 + T - 1) / T, T>>>(z4, 128, out, D_IN);
}

// round 8
// speedup vs baseline: 1.0468x; 1.0468x over previous
#include <cuda_runtime.h>
#include <cuda_bf16.h>
#include <cstdint>

#define NNODES 50000
#define NEDGES 200000
#define NGRAPH 2048
#define D_IN   64
#define D_H    1000
#define D_ENC  128

typedef __nv_bfloat16 bf16;

// ---------------- scratch (static device allocations; no cudaMalloc) --------
__device__ float g_aggx [NNODES * D_IN];
__device__ float g_aggy [NNODES * D_ENC];
__device__ float g_h2f  [NNODES * D_ENC];
__device__ float g_aggh2[NNODES * D_ENC];
__device__ float g_z2   [NNODES * 256];   // cols 0..127 rel, 128..255 root
__device__ float g_z4   [NNODES * 128];   // cols 0..63  rel, 64..127  root
__device__ float g_sums [NGRAPH * D_ENC];
__device__ float g_counts[NGRAPH];
__device__ int   g_ei32[2 * NEDGES];
__device__ int   g_batch32[NNODES];
__device__ int   g_is64;

__device__ __align__(16) bf16 g_x_h   [NNODES * D_IN],  g_x_l   [NNODES * D_IN];
__device__ __align__(16) bf16 g_aggx_h[NNODES * D_IN],  g_aggx_l[NNODES * D_IN];
__device__ __align__(16) bf16 g_h1_h  [(size_t)NNODES * D_H], g_h1_l[(size_t)NNODES * D_H];
__device__ __align__(16) bf16 g_h2_h  [NNODES * D_ENC], g_h2_l [NNODES * D_ENC];
__device__ __align__(16) bf16 g_ah2_h [NNODES * D_ENC], g_ah2_l[NNODES * D_ENC];
__device__ __align__(16) bf16 g_w1r_h[D_H * D_IN],  g_w1r_l[D_H * D_IN];
__device__ __align__(16) bf16 g_w1o_h[D_H * D_IN],  g_w1o_l[D_H * D_IN];
__device__ __align__(16) bf16 g_w2_h [256 * D_H],   g_w2_l [256 * D_H];
__device__ __align__(16) bf16 g_w3r_h[D_H * D_ENC], g_w3r_l[D_H * D_ENC];
__device__ __align__(16) bf16 g_w3o_h[D_H * D_ENC], g_w3o_l[D_H * D_ENC];
__device__ __align__(16) bf16 g_w4_h [128 * D_H],   g_w4_l [128 * D_H];

// ---------------- helpers ----------------------------------------------------
__device__ __forceinline__ void split_bf(float v, uint16_t& h, uint16_t& l) {
    bf16 hb = __float2bfloat16(v);
    bf16 lb = __float2bfloat16(v - __bfloat162float(hb));
    h = __bfloat16_as_ushort(hb);
    l = __bfloat16_as_ushort(lb);
}
__device__ __forceinline__ void mma16816(float* d, const uint32_t* a, uint32_t b0, uint32_t b1) {
    asm volatile(
        "mma.sync.aligned.m16n8k16.row.col.f32.bf16.bf16.f32 "
        "{%0,%1,%2,%3}, {%4,%5,%6,%7}, {%8,%9}, {%0,%1,%2,%3};"
        : "+f"(d[0]), "+f"(d[1]), "+f"(d[2]), "+f"(d[3])
        : "r"(a[0]), "r"(a[1]), "r"(a[2]), "r"(a[3]), "r"(b0), "r"(b1));
}
__device__ __forceinline__ uint32_t cvta_s(const void* p) {
    uint32_t a;
    asm("{ .reg .u64 t; cvta.to.shared.u64 t, %1; cvt.u32.u64 %0, t; }" : "=r"(a) : "l"(p));
    return a;
}
#define LDMX4(r, a) \
    asm volatile("ldmatrix.sync.aligned.m8n8.x4.shared.b16 {%0,%1,%2,%3}, [%4];" \
        : "=r"((r)[0]), "=r"((r)[1]), "=r"((r)[2]), "=r"((r)[3]) : "r"(a))

// ---------------- dtype detection + conversion ------------------------------
__global__ void detect_kernel(const int* __restrict__ ei_raw) {
    int odd_zero = 1;
    #pragma unroll
    for (int i = 0; i < 16; ++i)
        if (ei_raw[2 * i + 1] != 0) odd_zero = 0;
    g_is64 = odd_zero;
}
__global__ void convert_kernel(const int* __restrict__ ei_raw, const int* __restrict__ batch_raw) {
    int i = blockIdx.x * blockDim.x + threadIdx.x;
    int is64 = g_is64;
    if (i < 2 * NEDGES) g_ei32[i] = is64 ? ei_raw[2 * i] : ei_raw[i];
    if (i < NNODES)     g_batch32[i] = is64 ? batch_raw[2 * i] : batch_raw[i];
}

// ---------------- merged utility kernels -------------------------------------
__global__ void zero_all_kernel() {
    float4 z = make_float4(0.f, 0.f, 0.f, 0.f);
    float4* aggy  = reinterpret_cast<float4*>(g_aggy);
    float4* aggh2 = reinterpret_cast<float4*>(g_aggh2);
    float4* aggx  = reinterpret_cast<float4*>(g_aggx);
    float4* sums  = reinterpret_cast<float4*>(g_sums);
    float4* cnts  = reinterpret_cast<float4*>(g_counts);
    for (int i = blockIdx.x * blockDim.x + threadIdx.x; i < NNODES * D_ENC / 4;
         i += gridDim.x * blockDim.x) {
        aggy[i] = z;
        aggh2[i] = z;
        if (i < NNODES * D_IN / 4) aggx[i] = z;
        if (i < NGRAPH * D_ENC / 4) sums[i] = z;
        if (i < NGRAPH / 4) cnts[i] = z;
    }
}
__global__ void split_static_kernel(
    const float* __restrict__ w1r, const float* __restrict__ w1o,
    const float* __restrict__ w2r, const float* __restrict__ w2o,
    const float* __restrict__ w3r, const float* __restrict__ w3o,
    const float* __restrict__ w4r, const float* __restrict__ w4o,
    const float* __restrict__ x) {
    const int N1 = D_H * D_IN;
    const int N2 = 128 * D_H;
    const int N3 = D_H * D_ENC;
    const int N4 = 64 * D_H;
    const int TOT = 2 * N1 + 2 * N2 + 2 * N3 + 2 * N4 + NNODES * D_IN;
    for (int i = blockIdx.x * blockDim.x + threadIdx.x; i < TOT;
         i += gridDim.x * blockDim.x) {
        float v; bf16 *dh, *dl; int j = i;
        if (j < N1)            { v = w1r[j]; dh = g_w1r_h + j; dl = g_w1r_l + j; }
        else if ((j -= N1) < N1) { v = w1o[j]; dh = g_w1o_h + j; dl = g_w1o_l + j; }
        else if ((j -= N1) < N2) { v = w2r[j]; dh = g_w2_h + j; dl = g_w2_l + j; }
        else if ((j -= N2) < N2) { v = w2o[j]; dh = g_w2_h + N2 + j; dl = g_w2_l + N2 + j; }
        else if ((j -= N2) < N3) { v = w3r[j]; dh = g_w3r_h + j; dl = g_w3r_l + j; }
        else if ((j -= N3) < N3) { v = w3o[j]; dh = g_w3o_h + j; dl = g_w3o_l + j; }
        else if ((j -= N3) < N4) { v = w4r[j]; dh = g_w4_h + j; dl = g_w4_l + j; }
        else if ((j -= N4) < N4) { v = w4o[j]; dh = g_w4_h + N4 + j; dl = g_w4_l + N4 + j; }
        else { j -= N4;            v = x[j];   dh = g_x_h + j;  dl = g_x_l + j; }
        uint16_t h, l; split_bf(v, h, l);
        *dh = __ushort_as_bfloat16(h);
        *dl = __ushort_as_bfloat16(l);
    }
}
__global__ void split_kernel(const float* __restrict__ src, bf16* __restrict__ hi,
                             bf16* __restrict__ lo, int n) {
    for (int i = blockIdx.x * blockDim.x + threadIdx.x; i < n; i += gridDim.x * blockDim.x) {
        uint16_t h, l;
        split_bf(src[i], h, l);
        hi[i] = __ushort_as_bfloat16(h);
        lo[i] = __ushort_as_bfloat16(l);
    }
}
template <int F>
__global__ void edge_agg_kernel(const float* __restrict__ feat, int featStride,
                                float* __restrict__ out, int outStride) {
    constexpr int V = F / 4;
    int idx = blockIdx.x * blockDim.x + threadIdx.x;
    int e = idx / V;
    int f = (idx % V) * 4;
    if (e >= NEDGES) return;
    int s = g_ei32[e];
    int d = g_ei32[NEDGES + e];
    float4 v = *reinterpret_cast<const float4*>(&feat[(size_t)s * featStride + f]);
    float* o = &out[(size_t)d * outStride + f];
    atomicAdd(o + 0, v.x); atomicAdd(o + 1, v.y);
    atomicAdd(o + 2, v.z); atomicAdd(o + 3, v.w);
}
__global__ void combine_pool_kernel(const float* __restrict__ b2) {
    int idx = blockIdx.x * blockDim.x + threadIdx.x;
    if (idx >= NNODES * D_ENC) return;
    int i = idx >> 7, f = idx & 127;
    float v = fmaxf(g_aggy[idx] + g_z2[(size_t)i * 256 + 128 + f] + b2[f], 0.f);
    g_h2f[idx] = v;
    uint16_t h, l; split_bf(v, h, l);
    g_h2_h[idx] = __ushort_as_bfloat16(h);
    g_h2_l[idx] = __ushort_as_bfloat16(l);
    int b = g_batch32[i];
    atomicAdd(&g_sums[b * D_ENC + f], v);
    if (f == 0) atomicAdd(&g_counts[b], 1.f);
}
__global__ void encoded_kernel(float* __restrict__ enc) {
    int idx = blockIdx.x * blockDim.x + threadIdx.x;
    if (idx >= NGRAPH * D_ENC) return;
    int g = idx >> 7;
    enc[idx] = g_sums[idx] / fmaxf(g_counts[g], 1.f);
}
__global__ void out_init_kernel(float* __restrict__ out, const float* __restrict__ b4) {
    int idx = blockIdx.x * blockDim.x + threadIdx.x;
    if (idx >= NNODES * D_IN) return;
    int i = idx >> 6, f = idx & 63;
    out[idx] = g_z4[(size_t)i * 128 + 64 + f] + b4[f];
}

// ---------------- pipelined mma.sync bf16x3 GEMM (256x128 tile) --------------
// C[M,O] = sum_sides A_s[M,K] @ W_s[O,K]^T; A/W as bf16 hi/lo; fp32 accum.
// block tile 256x128; 512 threads = 16 warps (8m x 2n); warp tile 32x64.
// K-chunk 32, 2-stage cp.async, ldmatrix.x4 fragment loads. 1 CTA/SM.
#define CHUNK 32
#define SROW  80                      // 32 bf16 (64B) + 16B pad
#define A_SUB (256 * SROW)            // 20480
#define W_SUB (128 * SROW)            // 10240
#define STAGE (2 * A_SUB + 2 * W_SUB) // 61440
#define GSMEM (2 * STAGE)             // 122880

template <bool DUAL_A, bool RELU, bool BIAS, bool BF16OUT>
__global__ void __launch_bounds__(512, 1) mmagemm(
    float* __restrict__ Cf, bf16* __restrict__ Ch, bf16* __restrict__ Cl,
    const bf16* __restrict__ A1h, const bf16* __restrict__ A1l,
    const bf16* __restrict__ A2h, const bf16* __restrict__ A2l,
    const bf16* __restrict__ B1h, const bf16* __restrict__ B1l,
    const bf16* __restrict__ B2h, const bf16* __restrict__ B2l,
    const float* __restrict__ bias, int M, int K, int O) {

    extern __shared__ char smraw[];
    const uint32_t smemBase = cvta_s(smraw);

    const int tid = threadIdx.x;
    const int wid = tid >> 5, lane = tid & 31;
    const int g = lane >> 2, t = lane & 3;
    const int warpM = (wid & 7) * 32, warpN = (wid >> 3) * 64;
    const int rowBase = blockIdx.y * 256, colBase = blockIdx.x * 128;

    // ldmatrix per-lane offsets
    const int laneRowA = (lane & 7) + ((lane & 8) ? 8 : 0);
    const int aK = (lane & 16) ? 16 : 0;
    const int laneRowW = (lane & 7) + ((lane & 16) ? 8 : 0);
    const int wK = (lane & 8) ? 16 : 0;
    uint32_t aoff[2], woff[4];
    #pragma unroll
    for (int mi = 0; mi < 2; ++mi)
        aoff[mi] = (uint32_t)((warpM + mi * 16 + laneRowA) * SROW + aK);
    #pragma unroll
    for (int p = 0; p < 4; ++p)
        woff[p] = (uint32_t)((warpN + p * 16 + laneRowW) * SROW + wK);

    float acc[2][8][4];
    #pragma unroll
    for (int a = 0; a < 2; ++a)
        #pragma unroll
        for (int b = 0; b < 8; ++b)
            #pragma unroll
            for (int c = 0; c < 4; ++c) acc[a][b][c] = 0.f;

    const int KC = (K + CHUNK - 1) / CHUNK;
    const int C = (DUAL_A ? 2 : 1) * KC;

    auto loadChunk = [&](int i, int stage) {
        int sIdx = DUAL_A ? (i / KC) : 0;
        int c = i - sIdx * KC;
        int k0 = c * CHUNK;
        const bf16* Ah = (DUAL_A && sIdx) ? A2h : A1h;
        const bf16* Al = (DUAL_A && sIdx) ? A2l : A1l;
        const bf16* Wh = (DUAL_A && sIdx) ? B2h : B1h;
        const bf16* Wl = (DUAL_A && sIdx) ? B2l : B1l;
        uint32_t sb = smemBase + stage * STAGE;
        #pragma unroll
        for (int j = 0; j < 6; ++j) {
            int idx = tid + j * 512;          // 0..3071
            const bf16* src;
            uint32_t dst;
            int ok, gk;
            if (idx < 2048) {                 // A tiles: 2 x 256 rows x 4 sg
                int tile = idx >> 10, r = (idx >> 2) & 255, sg = idx & 3;
                gk = k0 + sg * 8;
                int gr = rowBase + r;
                ok = (gr < M) && (gk + 8 <= K);
                const bf16* base = tile ? Al : Ah;
                src = ok ? base + (size_t)gr * K + gk : base;
                dst = sb + tile * A_SUB + (uint32_t)(r * SROW + sg * 16);
            } else {                          // W tiles: 2 x 128 rows x 4 sg
                int rel = idx - 2048;
                int tile = rel >> 9, r = (rel >> 2) & 127, sg = rel & 3;
                gk = k0 + sg * 8;
                int gw = colBase + r;
                ok = (gw < O) && (gk + 8 <= K);
                const bf16* base = tile ? Wl : Wh;
                src = ok ? base + (size_t)gw * K + gk : base;
                dst = sb + 2 * A_SUB + tile * W_SUB + (uint32_t)(r * SROW + sg * 16);
            }
            int sz = ok ? 16 : 0;
            asm volatile("cp.async.cg.shared.global [%0], [%1], 16, %2;"
                         :: "r"(dst), "l"(src), "r"(sz) : "memory");
        }
        asm volatile("cp.async.commit_group;" ::: "memory");
    };

    auto computeChunk = [&](int stage) {
        uint32_t sb = smemBase + stage * STAGE;
        uint32_t bAh = sb, bAl = sb + A_SUB;
        uint32_t bWh = sb + 2 * A_SUB, bWl = sb + 2 * A_SUB + W_SUB;
        #pragma unroll
        for (int ks = 0; ks < 2; ++ks) {
            uint32_t koff = ks * 32;
            uint32_t ah[2][4], al[2][4];
            #pragma unroll
            for (int mi = 0; mi < 2; ++mi) {
                LDMX4(ah[mi], bAh + aoff[mi] + koff);
                LDMX4(al[mi], bAl + aoff[mi] + koff);
            }
            #pragma unroll
            for (int p = 0; p < 4; ++p) {
                uint32_t w[4];
                LDMX4(w, bWh + woff[p] + koff);
                mma16816(acc[0][2 * p],     ah[0], w[0], w[1]);
                mma16816(acc[1][2 * p],     ah[1], w[0], w[1]);
                mma16816(acc[0][2 * p + 1], ah[0], w[2], w[3]);
                mma16816(acc[1][2 * p + 1], ah[1], w[2], w[3]);
                mma16816(acc[0][2 * p],     al[0], w[0], w[1]);
                mma16816(acc[1][2 * p],     al[1], w[0], w[1]);
                mma16816(acc[0][2 * p + 1], al[0], w[2], w[3]);
                mma16816(acc[1][2 * p + 1], al[1], w[2], w[3]);
                uint32_t wl[4];
                LDMX4(wl, bWl + woff[p] + koff);
                mma16816(acc[0][2 * p],     ah[0], wl[0], wl[1]);
                mma16816(acc[1][2 * p],     ah[1], wl[0], wl[1]);
                mma16816(acc[0][2 * p + 1], ah[0], wl[2], wl[3]);
                mma16816(acc[1][2 * p + 1], ah[1], wl[2], wl[3]);
            }
        }
    };

    loadChunk(0, 0);
    for (int c = 0; c < C; ++c) {
        if (c + 1 < C) {
            loadChunk(c + 1, (c + 1) & 1);
            asm volatile("cp.async.wait_group 1;" ::: "memory");
        } else {
            asm volatile("cp.async.wait_group 0;" ::: "memory");
        }
        __syncthreads();
        computeChunk(c & 1);
        __syncthreads();
    }

    // ---- epilogue ----
    #pragma unroll
    for (int mi = 0; mi < 2; ++mi) {
        #pragma unroll
        for (int half = 0; half < 2; ++half) {
            int row = rowBase + warpM + mi * 16 + g + half * 8;
            if (row >= M) continue;
            #pragma unroll
            for (int ni = 0; ni < 8; ++ni) {
                int col = colBase + warpN + ni * 8 + 2 * t;
                if (col >= O) continue;
                float v0 = acc[mi][ni][half * 2 + 0];
                float v1 = acc[mi][ni][half * 2 + 1];
                if (BIAS) { v0 += bias[col]; if (col + 1 < O) v1 += bias[col + 1]; }
                if (RELU) { v0 = fmaxf(v0, 0.f); v1 = fmaxf(v1, 0.f); }
                bool pair = (col + 1 < O);
                size_t o = (size_t)row * O + col;
                if (BF16OUT) {
                    uint16_t h0, l0, h1, l1;
                    split_bf(v0, h0, l0);
                    split_bf(v1, h1, l1);
                    if (pair) {
                        *reinterpret_cast<uint32_t*>(&Ch[o]) = (uint32_t)h0 | ((uint32_t)h1 << 16);
                        *reinterpret_cast<uint32_t*>(&Cl[o]) = (uint32_t)l0 | ((uint32_t)l1 << 16);
                    } else {
                        Ch[o] = __ushort_as_bfloat16(h0);
                        Cl[o] = __ushort_as_bfloat16(l0);
                    }
                } else {
                    if (pair) *reinterpret_cast<float2*>(&Cf[o]) = make_float2(v0, v1);
                    else      Cf[o] = v0;
                }
            }
        }
    }
}

// ---------------- launch ----------------------------------------------------
extern "C" void kernel_launch(void* const* d_in, const int* in_sizes, int n_in,
                              void* d_out, int out_size) {
    const float* x         = (const float*)d_in[0];
    const int*   ei_raw    = (const int*)d_in[1];
    const int*   batch_raw = (const int*)d_in[2];
    const float* W1_rel = (const float*)d_in[3];
    const float* b1     = (const float*)d_in[4];
    const float* W1_root= (const float*)d_in[5];
    const float* W2_rel = (const float*)d_in[6];
    const float* b2     = (const float*)d_in[7];
    const float* W2_root= (const float*)d_in[8];
    const float* W3_rel = (const float*)d_in[9];
    const float* b3     = (const float*)d_in[10];
    const float* W3_root= (const float*)d_in[11];
    const float* W4_rel = (const float*)d_in[12];
    const float* b4     = (const float*)d_in[13];
    const float* W4_root= (const float*)d_in[14];

    float* out = (float*)d_out;
    float* enc = out + (size_t)NNODES * D_IN;

    float *aggx, *aggy, *h2f, *aggh2, *z2, *z4;
    bf16 *x_h, *x_l, *aggx_h, *aggx_l, *h1_h, *h1_l, *h2_h, *h2_l, *ah2_h, *ah2_l;
    bf16 *w1r_h, *w1r_l, *w1o_h, *w1o_l, *w2_h, *w2_l, *w3r_h, *w3r_l, *w3o_h, *w3o_l, *w4_h, *w4_l;
    cudaGetSymbolAddress((void**)&aggx, g_aggx);   cudaGetSymbolAddress((void**)&aggy, g_aggy);
    cudaGetSymbolAddress((void**)&h2f, g_h2f);     cudaGetSymbolAddress((void**)&aggh2, g_aggh2);
    cudaGetSymbolAddress((void**)&z2, g_z2);       cudaGetSymbolAddress((void**)&z4, g_z4);
    cudaGetSymbolAddress((void**)&x_h, g_x_h);     cudaGetSymbolAddress((void**)&x_l, g_x_l);
    cudaGetSymbolAddress((void**)&aggx_h, g_aggx_h); cudaGetSymbolAddress((void**)&aggx_l, g_aggx_l);
    cudaGetSymbolAddress((void**)&h1_h, g_h1_h);   cudaGetSymbolAddress((void**)&h1_l, g_h1_l);
    cudaGetSymbolAddress((void**)&h2_h, g_h2_h);   cudaGetSymbolAddress((void**)&h2_l, g_h2_l);
    cudaGetSymbolAddress((void**)&ah2_h, g_ah2_h); cudaGetSymbolAddress((void**)&ah2_l, g_ah2_l);
    cudaGetSymbolAddress((void**)&w1r_h, g_w1r_h); cudaGetSymbolAddress((void**)&w1r_l, g_w1r_l);
    cudaGetSymbolAddress((void**)&w1o_h, g_w1o_h); cudaGetSymbolAddress((void**)&w1o_l, g_w1o_l);
    cudaGetSymbolAddress((void**)&w2_h, g_w2_h);   cudaGetSymbolAddress((void**)&w2_l, g_w2_l);
    cudaGetSymbolAddress((void**)&w3r_h, g_w3r_h); cudaGetSymbolAddress((void**)&w3r_l, g_w3r_l);
    cudaGetSymbolAddress((void**)&w3o_h, g_w3o_h); cudaGetSymbolAddress((void**)&w3o_l, g_w3o_l);
    cudaGetSymbolAddress((void**)&w4_h, g_w4_h);   cudaGetSymbolAddress((void**)&w4_l, g_w4_l);

    const int T = 256;
    const int MB = (NNODES + 255) / 256;   // 196

    cudaFuncSetAttribute(mmagemm<true,  true,  true,  true >, cudaFuncAttributeMaxDynamicSharedMemorySize, GSMEM);
    cudaFuncSetAttribute(mmagemm<false, false, false, false>, cudaFuncAttributeMaxDynamicSharedMemorySize, GSMEM);

    // ---- setup
    detect_kernel<<<1, 1>>>(ei_raw);
    convert_kernel<<<(2 * NEDGES + T - 1) / T, T>>>(ei_raw, batch_raw);
    zero_all_kernel<<<1024, T>>>();
    split_static_kernel<<<1024, T>>>(W1_rel, W1_root, W2_rel, W2_root,
                                     W3_rel, W3_root, W4_rel, W4_root, x);

    // ---- L1: agg(x) then dual-A MMA -> h1 (bf16 hi/lo, relu, bias)
    edge_agg_kernel<64><<<(NEDGES * 16 + T - 1) / T, T>>>(x, D_IN, aggx, D_IN);
    split_kernel<<<1024, T>>>(aggx, aggx_h, aggx_l, NNODES * D_IN);
    {
        dim3 grid((D_H + 127) / 128, MB);
        mmagemm<true, true, true, true><<<grid, 512, GSMEM>>>(
            nullptr, h1_h, h1_l,
            aggx_h, aggx_l, x_h, x_l,
            w1r_h, w1r_l, w1o_h, w1o_l,
            b1, NNODES, D_IN, D_H);
    }

    // ---- L2: single-A MMA (K=1000, O=256 cat) -> z2 fp32
    {
        dim3 grid(2, MB);
        mmagemm<false, false, false, false><<<grid, 512, GSMEM>>>(
            z2, nullptr, nullptr,
            h1_h, h1_l, nullptr, nullptr,
            w2_h, w2_l, nullptr, nullptr,
            nullptr, NNODES, D_H, 256);
    }
    edge_agg_kernel<128><<<(NEDGES * 32 + T - 1) / T, T>>>(z2, 256, aggy, D_ENC);
    combine_pool_kernel<<<(NNODES * D_ENC + T - 1) / T, T>>>(b2);
    encoded_kernel<<<(NGRAPH * D_ENC + T - 1) / T, T>>>(enc);

    // ---- L3: agg(h2) then dual-A MMA -> h3 (reuse h1 buffers)
    edge_agg_kernel<128><<<(NEDGES * 32 + T - 1) / T, T>>>(h2f, D_ENC, aggh2, D_ENC);
    split_kernel<<<1024, T>>>(aggh2, ah2_h, ah2_l, NNODES * D_ENC);
    {
        dim3 grid((D_H + 127) / 128, MB);
        mmagemm<true, true, true, true><<<grid, 512, GSMEM>>>(
            nullptr, h1_h, h1_l,
            ah2_h, ah2_l, h2_h, h2_l,
            w3r_h, w3r_l, w3o_h, w3o_l,
            b3, NNODES, D_ENC, D_H);
    }

    // ---- L4: single-A MMA (K=1000, O=128 cat) -> z4 fp32
    {
        dim3 grid(1, MB);
        mmagemm<false, false, false, false><<<grid, 512, GSMEM>>>(
            z4, nullptr, nullptr,
            h1_h, h1_l, nullptr, nullptr,
            w4_h, w4_l, nullptr, nullptr,
            nullptr, NNODES, D_H, 128);
    }
    out_init_kernel<<<(NNODES * D_IN + T - 1) / T, T>>>(out, b4);
    edge_agg_kernel<64><<<(NEDGES * 16 + T - 1) / T, T>>>(z4, 128, out, D_IN);
}

// round 9
// speedup vs baseline: 1.2715x; 1.2147x over previous
#include <cuda_runtime.h>
#include <cuda_bf16.h>
#include <cstdint>

#define NNODES 50000
#define NEDGES 200000
#define NGRAPH 2048
#define D_IN   64
#define D_H    1000
#define D_ENC  128

typedef __nv_bfloat16 bf16;

// ---------------- scratch (static device allocations; no cudaMalloc) --------
__device__ float g_aggx [NNODES * D_IN];
__device__ float g_aggy [NNODES * D_ENC];
__device__ float g_h2f  [NNODES * D_ENC];
__device__ float g_aggh2[NNODES * D_ENC];
__device__ float g_z2   [NNODES * 256];   // cols 0..127 rel, 128..255 root
__device__ float g_z4   [NNODES * 128];   // cols 0..63  rel, 64..127  root
__device__ float g_sums [NGRAPH * D_ENC];
__device__ float g_counts[NGRAPH];
__device__ int   g_ei32[2 * NEDGES];
__device__ int   g_batch32[NNODES];
__device__ int   g_is64;

__device__ __align__(16) bf16 g_x_h   [NNODES * D_IN],  g_x_l   [NNODES * D_IN];
__device__ __align__(16) bf16 g_aggx_h[NNODES * D_IN],  g_aggx_l[NNODES * D_IN];
__device__ __align__(16) bf16 g_h1_h  [(size_t)NNODES * D_H], g_h1_l[(size_t)NNODES * D_H];
__device__ __align__(16) bf16 g_h2_h  [NNODES * D_ENC], g_h2_l [NNODES * D_ENC];
__device__ __align__(16) bf16 g_ah2_h [NNODES * D_ENC], g_ah2_l[NNODES * D_ENC];
__device__ __align__(16) bf16 g_w1r_h[D_H * D_IN],  g_w1r_l[D_H * D_IN];
__device__ __align__(16) bf16 g_w1o_h[D_H * D_IN],  g_w1o_l[D_H * D_IN];
__device__ __align__(16) bf16 g_w2_h [256 * D_H],   g_w2_l [256 * D_H];
__device__ __align__(16) bf16 g_w3r_h[D_H * D_ENC], g_w3r_l[D_H * D_ENC];
__device__ __align__(16) bf16 g_w3o_h[D_H * D_ENC], g_w3o_l[D_H * D_ENC];
__device__ __align__(16) bf16 g_w4_h [128 * D_H],   g_w4_l [128 * D_H];

// ---------------- helpers ----------------------------------------------------
// fast paired hi/lo split: returns {packed_hi(bf16x2), packed_lo(bf16x2)}
// element0 in low 16 bits (memory order for [e0, e1]).
__device__ __forceinline__ uint2 split2(float v0, float v1) {
    uint32_t pH;
    asm("cvt.rn.bf16x2.f32 %0, %1, %2;" : "=r"(pH) : "f"(v1), "f"(v0));
    float h0 = __uint_as_float(pH << 16);
    float h1 = __uint_as_float(pH & 0xffff0000u);
    float r0 = v0 - h0, r1 = v1 - h1;
    uint32_t pL;
    asm("cvt.rn.bf16x2.f32 %0, %1, %2;" : "=r"(pL) : "f"(r1), "f"(r0));
    return make_uint2(pH, pL);
}
__device__ __forceinline__ void mma16816(float* d, const uint32_t* a, uint32_t b0, uint32_t b1) {
    asm volatile(
        "mma.sync.aligned.m16n8k16.row.col.f32.bf16.bf16.f32 "
        "{%0,%1,%2,%3}, {%4,%5,%6,%7}, {%8,%9}, {%0,%1,%2,%3};"
        : "+f"(d[0]), "+f"(d[1]), "+f"(d[2]), "+f"(d[3])
        : "r"(a[0]), "r"(a[1]), "r"(a[2]), "r"(a[3]), "r"(b0), "r"(b1));
}
__device__ __forceinline__ uint32_t cvta_s(const void* p) {
    uint32_t a;
    asm("{ .reg .u64 t; cvta.to.shared.u64 t, %1; cvt.u32.u64 %0, t; }" : "=r"(a) : "l"(p));
    return a;
}
#define LDMX4(r, a) \
    asm volatile("ldmatrix.sync.aligned.m8n8.x4.shared.b16 {%0,%1,%2,%3}, [%4];" \
        : "=r"((r)[0]), "=r"((r)[1]), "=r"((r)[2]), "=r"((r)[3]) : "r"(a))

// ---------------- dtype detection + conversion ------------------------------
__global__ void detect_kernel(const int* __restrict__ ei_raw) {
    int odd_zero = 1;
    #pragma unroll
    for (int i = 0; i < 16; ++i)
        if (ei_raw[2 * i + 1] != 0) odd_zero = 0;
    g_is64 = odd_zero;
}
__global__ void convert_kernel(const int* __restrict__ ei_raw, const int* __restrict__ batch_raw) {
    int i = blockIdx.x * blockDim.x + threadIdx.x;
    int is64 = g_is64;
    if (i < 2 * NEDGES) g_ei32[i] = is64 ? ei_raw[2 * i] : ei_raw[i];
    if (i < NNODES)     g_batch32[i] = is64 ? batch_raw[2 * i] : batch_raw[i];
}

// ---------------- merged utility kernels -------------------------------------
__global__ void zero_all_kernel() {
    float4 z = make_float4(0.f, 0.f, 0.f, 0.f);
    float4* aggy  = reinterpret_cast<float4*>(g_aggy);
    float4* aggh2 = reinterpret_cast<float4*>(g_aggh2);
    float4* aggx  = reinterpret_cast<float4*>(g_aggx);
    float4* sums  = reinterpret_cast<float4*>(g_sums);
    float4* cnts  = reinterpret_cast<float4*>(g_counts);
    for (int i = blockIdx.x * blockDim.x + threadIdx.x; i < NNODES * D_ENC / 4;
         i += gridDim.x * blockDim.x) {
        aggy[i] = z;
        aggh2[i] = z;
        if (i < NNODES * D_IN / 4) aggx[i] = z;
        if (i < NGRAPH * D_ENC / 4) sums[i] = z;
        if (i < NGRAPH / 4) cnts[i] = z;
    }
}
// split all weights + x in one launch; 2 elements per iteration (all sections even)
__global__ void split_static_kernel(
    const float* __restrict__ w1r, const float* __restrict__ w1o,
    const float* __restrict__ w2r, const float* __restrict__ w2o,
    const float* __restrict__ w3r, const float* __restrict__ w3o,
    const float* __restrict__ w4r, const float* __restrict__ w4o,
    const float* __restrict__ x) {
    const int H1 = D_H * D_IN / 2;
    const int H2 = 128 * D_H / 2;
    const int H3 = D_H * D_ENC / 2;
    const int H4 = 64 * D_H / 2;
    const int HX = NNODES * D_IN / 2;
    const int TOTP = 2 * H1 + 2 * H2 + 2 * H3 + 2 * H4 + HX;
    for (int p = blockIdx.x * blockDim.x + threadIdx.x; p < TOTP;
         p += gridDim.x * blockDim.x) {
        const float* src; bf16 *dh, *dl; int j = p;
        if (j < H1)              { src = w1r; dh = g_w1r_h; dl = g_w1r_l; }
        else if ((j -= H1) < H1) { src = w1o; dh = g_w1o_h; dl = g_w1o_l; }
        else if ((j -= H1) < H2) { src = w2r; dh = g_w2_h; dl = g_w2_l; }
        else if ((j -= H2) < H2) { src = w2o; dh = g_w2_h + 2 * H2; dl = g_w2_l + 2 * H2; }
        else if ((j -= H2) < H3) { src = w3r; dh = g_w3r_h; dl = g_w3r_l; }
        else if ((j -= H3) < H3) { src = w3o; dh = g_w3o_h; dl = g_w3o_l; }
        else if ((j -= H3) < H4) { src = w4r; dh = g_w4_h; dl = g_w4_l; }
        else if ((j -= H4) < H4) { src = w4o; dh = g_w4_h + 2 * H4; dl = g_w4_l + 2 * H4; }
        else { j -= H4;            src = x;   dh = g_x_h;  dl = g_x_l; }
        int e = j * 2;
        float2 v = *reinterpret_cast<const float2*>(&src[e]);
        uint2 s = split2(v.x, v.y);
        *reinterpret_cast<uint32_t*>(&dh[e]) = s.x;
        *reinterpret_cast<uint32_t*>(&dl[e]) = s.y;
    }
}
__global__ void split_kernel(const float* __restrict__ src, bf16* __restrict__ hi,
                             bf16* __restrict__ lo, int n) {
    for (int e = (blockIdx.x * blockDim.x + threadIdx.x) * 2; e < n;
         e += gridDim.x * blockDim.x * 2) {
        float2 v = *reinterpret_cast<const float2*>(&src[e]);
        uint2 s = split2(v.x, v.y);
        *reinterpret_cast<uint32_t*>(&hi[e]) = s.x;
        *reinterpret_cast<uint32_t*>(&lo[e]) = s.y;
    }
}
template <int F>
__global__ void edge_agg_kernel(const float* __restrict__ feat, int featStride,
                                float* __restrict__ out, int outStride) {
    constexpr int V = F / 4;
    int idx = blockIdx.x * blockDim.x + threadIdx.x;
    int e = idx / V;
    int f = (idx % V) * 4;
    if (e >= NEDGES) return;
    int s = g_ei32[e];
    int d = g_ei32[NEDGES + e];
    float4 v = *reinterpret_cast<const float4*>(&feat[(size_t)s * featStride + f]);
    float* o = &out[(size_t)d * outStride + f];
    atomicAdd(o + 0, v.x); atomicAdd(o + 1, v.y);
    atomicAdd(o + 2, v.z); atomicAdd(o + 3, v.w);
}
// fused: h2 = relu(aggy + z2_root + b2); fp32 + packed hi/lo; pool (2 el/thread)
__global__ void combine_pool_kernel(const float* __restrict__ b2) {
    int idx = blockIdx.x * blockDim.x + threadIdx.x;
    if (idx >= NNODES * 64) return;
    int i = idx >> 6, f = (idx & 63) * 2;
    float2 ag = *reinterpret_cast<const float2*>(&g_aggy[i * D_ENC + f]);
    float2 zr = *reinterpret_cast<const float2*>(&g_z2[(size_t)i * 256 + 128 + f]);
    float2 bb = *reinterpret_cast<const float2*>(&b2[f]);
    float v0 = fmaxf(ag.x + zr.x + bb.x, 0.f);
    float v1 = fmaxf(ag.y + zr.y + bb.y, 0.f);
    *reinterpret_cast<float2*>(&g_h2f[i * D_ENC + f]) = make_float2(v0, v1);
    uint2 s = split2(v0, v1);
    *reinterpret_cast<uint32_t*>(&g_h2_h[i * D_ENC + f]) = s.x;
    *reinterpret_cast<uint32_t*>(&g_h2_l[i * D_ENC + f]) = s.y;
    int b = g_batch32[i];
    atomicAdd(&g_sums[b * D_ENC + f], v0);
    atomicAdd(&g_sums[b * D_ENC + f + 1], v1);
    if (f == 0) atomicAdd(&g_counts[b], 1.f);
}
__global__ void encoded_kernel(float* __restrict__ enc) {
    int idx = blockIdx.x * blockDim.x + threadIdx.x;
    if (idx >= NGRAPH * D_ENC) return;
    int g = idx >> 7;
    enc[idx] = g_sums[idx] / fmaxf(g_counts[g], 1.f);
}
__global__ void out_init_kernel(float* __restrict__ out, const float* __restrict__ b4) {
    int idx = blockIdx.x * blockDim.x + threadIdx.x;
    if (idx >= NNODES * D_IN) return;
    int i = idx >> 6, f = idx & 63;
    out[idx] = g_z4[(size_t)i * 128 + 64 + f] + b4[f];
}

// ---------------- pipelined mma.sync bf16x3 GEMM (R6 config) -----------------
// block 128x128; 8 warps (4m x 2n); warp tile 32x64.
// K-chunk 32, 2-stage cp.async pipeline, ldmatrix.x4 fragment loads, 2 CTA/SM.
#define CHUNK 32
#define SROW  80
#define GTILE (128 * SROW)        // 10240
#define GSTAGE (4 * GTILE)        // 40960

template <bool DUAL_A, bool RELU, bool BIAS, bool BF16OUT>
__global__ void __launch_bounds__(256, 2) mmagemm(
    float* __restrict__ Cf, bf16* __restrict__ Ch, bf16* __restrict__ Cl,
    const bf16* __restrict__ A1h, const bf16* __restrict__ A1l,
    const bf16* __restrict__ A2h, const bf16* __restrict__ A2l,
    const bf16* __restrict__ B1h, const bf16* __restrict__ B1l,
    const bf16* __restrict__ B2h, const bf16* __restrict__ B2l,
    const float* __restrict__ bias, int M, int K, int O) {

    extern __shared__ char smraw[];
    const uint32_t smemBase = cvta_s(smraw);

    const int tid = threadIdx.x;
    const int wid = tid >> 5, lane = tid & 31;
    const int g = lane >> 2, t = lane & 3;
    const int warpM = (wid & 3) * 32, warpN = (wid >> 2) * 64;
    const int rowBase = blockIdx.y * 128, colBase = blockIdx.x * 128;

    const int laneRowA = (lane & 7) + ((lane & 8) ? 8 : 0);
    const int aK = (lane & 16) ? 16 : 0;
    const int laneRowW = (lane & 7) + ((lane & 16) ? 8 : 0);
    const int wK = (lane & 8) ? 16 : 0;
    uint32_t aoff[2], woff[4];
    #pragma unroll
    for (int mi = 0; mi < 2; ++mi)
        aoff[mi] = (uint32_t)((warpM + mi * 16 + laneRowA) * SROW + aK);
    #pragma unroll
    for (int p = 0; p < 4; ++p)
        woff[p] = (uint32_t)((warpN + p * 16 + laneRowW) * SROW + wK);

    float acc[2][8][4];
    #pragma unroll
    for (int a = 0; a < 2; ++a)
        #pragma unroll
        for (int b = 0; b < 8; ++b)
            #pragma unroll
            for (int c = 0; c < 4; ++c) acc[a][b][c] = 0.f;

    const int KC = (K + CHUNK - 1) / CHUNK;
    const int C = (DUAL_A ? 2 : 1) * KC;

    auto loadChunk = [&](int i, int stage) {
        int sIdx = DUAL_A ? (i / KC) : 0;
        int c = i - sIdx * KC;
        int k0 = c * CHUNK;
        const bf16* Ah = (DUAL_A && sIdx) ? A2h : A1h;
        const bf16* Al = (DUAL_A && sIdx) ? A2l : A1l;
        const bf16* Wh = (DUAL_A && sIdx) ? B2h : B1h;
        const bf16* Wl = (DUAL_A && sIdx) ? B2l : B1l;
        uint32_t sb = smemBase + stage * GSTAGE;
        #pragma unroll
        for (int j = 0; j < 8; ++j) {
            int idx = tid + j * 256;
            int tile = idx >> 9;
            int r = (idx >> 2) & 127;
            int sg = idx & 3;
            int gk = k0 + sg * 8;
            const bf16* src;
            int ok;
            if (tile < 2) {
                int gr = rowBase + r;
                ok = (gr < M) && (gk + 8 <= K);
                const bf16* base = tile ? Al : Ah;
                src = ok ? base + (size_t)gr * K + gk : base;
            } else {
                int gw = colBase + r;
                ok = (gw < O) && (gk + 8 <= K);
                const bf16* base = (tile == 2) ? Wh : Wl;
                src = ok ? base + (size_t)gw * K + gk : base;
            }
            uint32_t dst = sb + tile * GTILE + (uint32_t)(r * SROW + sg * 16);
            int sz = ok ? 16 : 0;
            asm volatile("cp.async.cg.shared.global [%0], [%1], 16, %2;"
                         :: "r"(dst), "l"(src), "r"(sz) : "memory");
        }
        asm volatile("cp.async.commit_group;" ::: "memory");
    };

    auto computeChunk = [&](int stage) {
        uint32_t sb = smemBase + stage * GSTAGE;
        uint32_t bAh = sb, bAl = sb + GTILE, bWh = sb + 2 * GTILE, bWl = sb + 3 * GTILE;
        #pragma unroll
        for (int ks = 0; ks < 2; ++ks) {
            uint32_t koff = ks * 32;
            uint32_t ah[2][4], al[2][4];
            #pragma unroll
            for (int mi = 0; mi < 2; ++mi) {
                LDMX4(ah[mi], bAh + aoff[mi] + koff);
                LDMX4(al[mi], bAl + aoff[mi] + koff);
            }
            #pragma unroll
            for (int p = 0; p < 4; ++p) {
                uint32_t w[4];
                LDMX4(w, bWh + woff[p] + koff);
                mma16816(acc[0][2 * p],     ah[0], w[0], w[1]);
                mma16816(acc[1][2 * p],     ah[1], w[0], w[1]);
                mma16816(acc[0][2 * p + 1], ah[0], w[2], w[3]);
                mma16816(acc[1][2 * p + 1], ah[1], w[2], w[3]);
                mma16816(acc[0][2 * p],     al[0], w[0], w[1]);
                mma16816(acc[1][2 * p],     al[1], w[0], w[1]);
                mma16816(acc[0][2 * p + 1], al[0], w[2], w[3]);
                mma16816(acc[1][2 * p + 1], al[1], w[2], w[3]);
                uint32_t wl[4];
                LDMX4(wl, bWl + woff[p] + koff);
                mma16816(acc[0][2 * p],     ah[0], wl[0], wl[1]);
                mma16816(acc[1][2 * p],     ah[1], wl[0], wl[1]);
                mma16816(acc[0][2 * p + 1], ah[0], wl[2], wl[3]);
                mma16816(acc[1][2 * p + 1], ah[1], wl[2], wl[3]);
            }
        }
    };

    loadChunk(0, 0);
    for (int c = 0; c < C; ++c) {
        if (c + 1 < C) {
            loadChunk(c + 1, (c + 1) & 1);
            asm volatile("cp.async.wait_group 1;" ::: "memory");
        } else {
            asm volatile("cp.async.wait_group 0;" ::: "memory");
        }
        __syncthreads();
        computeChunk(c & 1);
        __syncthreads();
    }

    // ---- epilogue (cols always even; pair stores unconditional) ----
    #pragma unroll
    for (int mi = 0; mi < 2; ++mi) {
        #pragma unroll
        for (int half = 0; half < 2; ++half) {
            int row = rowBase + warpM + mi * 16 + g + half * 8;
            if (row >= M) continue;
            #pragma unroll
            for (int ni = 0; ni < 8; ++ni) {
                int col = colBase + warpN + ni * 8 + 2 * t;
                if (col >= O) continue;
                float v0 = acc[mi][ni][half * 2 + 0];
                float v1 = acc[mi][ni][half * 2 + 1];
                if (BIAS) {
                    float2 bb = *reinterpret_cast<const float2*>(&bias[col]);
                    v0 += bb.x; v1 += bb.y;
                }
                if (RELU) { v0 = fmaxf(v0, 0.f); v1 = fmaxf(v1, 0.f); }
                size_t o = (size_t)row * O + col;
                if (BF16OUT) {
                    uint2 s = split2(v0, v1);
                    *reinterpret_cast<uint32_t*>(&Ch[o]) = s.x;
                    *reinterpret_cast<uint32_t*>(&Cl[o]) = s.y;
                } else {
                    *reinterpret_cast<float2*>(&Cf[o]) = make_float2(v0, v1);
                }
            }
        }
    }
}

// ---------------- launch ----------------------------------------------------
extern "C" void kernel_launch(void* const* d_in, const int* in_sizes, int n_in,
                              void* d_out, int out_size) {
    const float* x         = (const float*)d_in[0];
    const int*   ei_raw    = (const int*)d_in[1];
    const int*   batch_raw = (const int*)d_in[2];
    const float* W1_rel = (const float*)d_in[3];
    const float* b1     = (const float*)d_in[4];
    const float* W1_root= (const float*)d_in[5];
    const float* W2_rel = (const float*)d_in[6];
    const float* b2     = (const float*)d_in[7];
    const float* W2_root= (const float*)d_in[8];
    const float* W3_rel = (const float*)d_in[9];
    const float* b3     = (const float*)d_in[10];
    const float* W3_root= (const float*)d_in[11];
    const float* W4_rel = (const float*)d_in[12];
    const float* b4     = (const float*)d_in[13];
    const float* W4_root= (const float*)d_in[14];

    float* out = (float*)d_out;
    float* enc = out + (size_t)NNODES * D_IN;

    float *aggx, *aggy, *h2f, *aggh2, *z2, *z4;
    bf16 *x_h, *x_l, *aggx_h, *aggx_l, *h1_h, *h1_l, *h2_h, *h2_l, *ah2_h, *ah2_l;
    bf16 *w1r_h, *w1r_l, *w1o_h, *w1o_l, *w2_h, *w2_l, *w3r_h, *w3r_l, *w3o_h, *w3o_l, *w4_h, *w4_l;
    cudaGetSymbolAddress((void**)&aggx, g_aggx);   cudaGetSymbolAddress((void**)&aggy, g_aggy);
    cudaGetSymbolAddress((void**)&h2f, g_h2f);     cudaGetSymbolAddress((void**)&aggh2, g_aggh2);
    cudaGetSymbolAddress((void**)&z2, g_z2);       cudaGetSymbolAddress((void**)&z4, g_z4);
    cudaGetSymbolAddress((void**)&x_h, g_x_h);     cudaGetSymbolAddress((void**)&x_l, g_x_l);
    cudaGetSymbolAddress((void**)&aggx_h, g_aggx_h); cudaGetSymbolAddress((void**)&aggx_l, g_aggx_l);
    cudaGetSymbolAddress((void**)&h1_h, g_h1_h);   cudaGetSymbolAddress((void**)&h1_l, g_h1_l);
    cudaGetSymbolAddress((void**)&h2_h, g_h2_h);   cudaGetSymbolAddress((void**)&h2_l, g_h2_l);
    cudaGetSymbolAddress((void**)&ah2_h, g_ah2_h); cudaGetSymbolAddress((void**)&ah2_l, g_ah2_l);
    cudaGetSymbolAddress((void**)&w1r_h, g_w1r_h); cudaGetSymbolAddress((void**)&w1r_l, g_w1r_l);
    cudaGetSymbolAddress((void**)&w1o_h, g_w1o_h); cudaGetSymbolAddress((void**)&w1o_l, g_w1o_l);
    cudaGetSymbolAddress((void**)&w2_h, g_w2_h);   cudaGetSymbolAddress((void**)&w2_l, g_w2_l);
    cudaGetSymbolAddress((void**)&w3r_h, g_w3r_h); cudaGetSymbolAddress((void**)&w3r_l, g_w3r_l);
    cudaGetSymbolAddress((void**)&w3o_h, g_w3o_h); cudaGetSymbolAddress((void**)&w3o_l, g_w3o_l);
    cudaGetSymbolAddress((void**)&w4_h, g_w4_h);   cudaGetSymbolAddress((void**)&w4_l, g_w4_l);

    const int T = 256;
    const int MB = (NNODES + 127) / 128;   // 391
    constexpr int SMEM = 2 * GSTAGE;       // 81920

    cudaFuncSetAttribute(mmagemm<true,  true,  true,  true >, cudaFuncAttributeMaxDynamicSharedMemorySize, SMEM);
    cudaFuncSetAttribute(mmagemm<false, false, false, false>, cudaFuncAttributeMaxDynamicSharedMemorySize, SMEM);

    // ---- setup
    detect_kernel<<<1, 1>>>(ei_raw);
    convert_kernel<<<(2 * NEDGES + T - 1) / T, T>>>(ei_raw, batch_raw);
    zero_all_kernel<<<1024, T>>>();
    split_static_kernel<<<1024, T>>>(W1_rel, W1_root, W2_rel, W2_root,
                                     W3_rel, W3_root, W4_rel, W4_root, x);

    // ---- L1: agg(x) then dual-A MMA -> h1 (bf16 hi/lo, relu, bias)
    edge_agg_kernel<64><<<(NEDGES * 16 + T - 1) / T, T>>>(x, D_IN, aggx, D_IN);
    split_kernel<<<512, T>>>(aggx, aggx_h, aggx_l, NNODES * D_IN);
    {
        dim3 grid((D_H + 127) / 128, MB);
        mmagemm<true, true, true, true><<<grid, T, SMEM>>>(
            nullptr, h1_h, h1_l,
            aggx_h, aggx_l, x_h, x_l,
            w1r_h, w1r_l, w1o_h, w1o_l,
            b1, NNODES, D_IN, D_H);
    }

    // ---- L2: single-A MMA (K=1000, O=256 cat) -> z2 fp32
    {
        dim3 grid(2, MB);
        mmagemm<false, false, false, false><<<grid, T, SMEM>>>(
            z2, nullptr, nullptr,
            h1_h, h1_l, nullptr, nullptr,
            w2_h, w2_l, nullptr, nullptr,
            nullptr, NNODES, D_H, 256);
    }
    edge_agg_kernel<128><<<(NEDGES * 32 + T - 1) / T, T>>>(z2, 256, aggy, D_ENC);
    combine_pool_kernel<<<(NNODES * 64 + T - 1) / T, T>>>(b2);
    encoded_kernel<<<(NGRAPH * D_ENC + T - 1) / T, T>>>(enc);

    // ---- L3: agg(h2) then dual-A MMA -> h3 (reuse h1 buffers)
    edge_agg_kernel<128><<<(NEDGES * 32 + T - 1) / T, T>>>(h2f, D_ENC, aggh2, D_ENC);
    split_kernel<<<512, T>>>(aggh2, ah2_h, ah2_l, NNODES * D_ENC);
    {
        dim3 grid((D_H + 127) / 128, MB);
        mmagemm<true, true, true, true><<<grid, T, SMEM>>>(
            nullptr, h1_h, h1_l,
            ah2_h, ah2_l, h2_h, h2_l,
            w3r_h, w3r_l, w3o_h, w3o_l,
            b3, NNODES, D_ENC, D_H);
    }

    // ---- L4: single-A MMA (K=1000, O=128 cat) -> z4 fp32
    {
        dim3 grid(1, MB);
        mmagemm<false, false, false, false><<<grid, T, SMEM>>>(
            z4, nullptr, nullptr,
            h1_h, h1_l, nullptr, nullptr,
            w4_h, w4_l, nullptr, nullptr,
            nullptr, NNODES, D_H, 128);
    }
    out_init_kernel<<<(NNODES * D_IN + T - 1) / T, T>>>(out, b4);
    edge_agg_kernel<64><<<(NEDGES * 16 + T - 1) / T, T>>>(z4, 128, out, D_IN);
}